// round 3
// baseline (speedup 1.0000x reference)
#include <cuda_runtime.h>
#include <cuda_bf16.h>
#include <cstdint>

// Problem constants
#define BB 2048
#define SS 256
#define DD 768
#define CC 100

// Scratch (no cudaMalloc allowed)
__device__ float g_bow[(size_t)BB * DD];
__device__ float g_h[(size_t)BB * DD];

// ---------------------------------------------------------------------------
// Stage 1: embedding gather + masked mean pooling.
// One block per sample. 192 threads, each owns one float4 (768 = 192*4).
// NOTE: ids/mask are int32 (JAX demotes int64 without x64 mode).
// ---------------------------------------------------------------------------
__global__ __launch_bounds__(192) void pool_kernel(
    const int* __restrict__ ids,
    const int* __restrict__ mask,
    const float* __restrict__ emb,
    float* __restrict__ bow)
{
    const int b = blockIdx.x;
    const int t = threadIdx.x;  // 0..191

    __shared__ int s_ids[SS];   // id if valid else -1

    const int* id_row = ids  + (size_t)b * SS;
    const int* m_row  = mask + (size_t)b * SS;
    for (int s = t; s < SS; s += 192) {
        s_ids[s] = (m_row[s] != 0) ? id_row[s] : -1;
    }
    __syncthreads();

    float4 acc = make_float4(0.f, 0.f, 0.f, 0.f);
    int cnt = 0;
#pragma unroll 8
    for (int s = 0; s < SS; s++) {
        int id = s_ids[s];
        if (id >= 0) {
            const float4 v = *((const float4*)(emb + (size_t)id * DD) + t);
            acc.x += v.x; acc.y += v.y; acc.z += v.z; acc.w += v.w;
            cnt++;
        }
    }
    const float inv = 1.0f / (float)cnt;   // cnt >= 1 guaranteed (mask[:,0]=1)
    acc.x *= inv; acc.y *= inv; acc.z *= inv; acc.w *= inv;
    *((float4*)(bow + (size_t)b * DD) + t) = acc;
}

// ---------------------------------------------------------------------------
// Tiled fp32 GEMM:  C = op(A[M,K] @ B[K,N] + bias),  op = relu optionally.
// BM=64, BN=64, BK=16, 256 threads, 4x4 register tile per thread.
// GUARD handles N not multiple of tile (gemm2, N=100).
// Optionally duplicates output to Cout2 (for the (scores, scores) tuple).
// ---------------------------------------------------------------------------
template<bool RELU, bool GUARD>
__global__ __launch_bounds__(256) void gemm_kernel(
    const float* __restrict__ A,
    const float* __restrict__ Bm,
    const float* __restrict__ bias,
    float* __restrict__ Cout,
    float* __restrict__ Cout2,
    int M, int N, int K)
{
    const int BM = 64, BN = 64, BK = 16;
    __shared__ float As[BK][BM + 4];   // +4 pad: avoid bank conflicts on transposed store
    __shared__ float Bs[BK][BN];

    const int tid = threadIdx.x;           // 0..255
    const int tx  = tid & 15;              // 0..15 -> col group
    const int ty  = tid >> 4;              // 0..15 -> row group

    const int block_row = blockIdx.y * BM;
    const int block_col = blockIdx.x * BN;

    // A tile load mapping: 64 rows x 16 k -> one float4 per thread
    const int a_row = tid >> 2;            // 0..63
    const int a_c4  = (tid & 3) * 4;       // 0,4,8,12
    // B tile load mapping: 16 rows x 64 cols -> one float4 per thread
    const int b_row = tid >> 4;            // 0..15
    const int b_col = (tid & 15) * 4;      // 0..60

    float acc[4][4];
#pragma unroll
    for (int i = 0; i < 4; i++)
#pragma unroll
        for (int j = 0; j < 4; j++) acc[i][j] = 0.f;

    for (int k0 = 0; k0 < K; k0 += BK) {
        // Load A tile (rows always valid: M multiple of 64 here)
        {
            const float4 av = *(const float4*)(A + (size_t)(block_row + a_row) * K + k0 + a_c4);
            As[a_c4 + 0][a_row] = av.x;
            As[a_c4 + 1][a_row] = av.y;
            As[a_c4 + 2][a_row] = av.z;
            As[a_c4 + 3][a_row] = av.w;
        }
        // Load B tile
        if (!GUARD) {
            *(float4*)&Bs[b_row][b_col] =
                *(const float4*)(Bm + (size_t)(k0 + b_row) * N + block_col + b_col);
        } else {
            const int col = block_col + b_col;
            const float* src = Bm + (size_t)(k0 + b_row) * N;
            Bs[b_row][b_col + 0] = (col + 0 < N) ? src[col + 0] : 0.f;
            Bs[b_row][b_col + 1] = (col + 1 < N) ? src[col + 1] : 0.f;
            Bs[b_row][b_col + 2] = (col + 2 < N) ? src[col + 2] : 0.f;
            Bs[b_row][b_col + 3] = (col + 3 < N) ? src[col + 3] : 0.f;
        }
        __syncthreads();

#pragma unroll
        for (int k = 0; k < BK; k++) {
            float a[4], bb[4];
#pragma unroll
            for (int i = 0; i < 4; i++) a[i]  = As[k][ty * 4 + i];
#pragma unroll
            for (int j = 0; j < 4; j++) bb[j] = Bs[k][tx * 4 + j];
#pragma unroll
            for (int i = 0; i < 4; i++)
#pragma unroll
                for (int j = 0; j < 4; j++)
                    acc[i][j] = fmaf(a[i], bb[j], acc[i][j]);
        }
        __syncthreads();
    }

    // Epilogue
#pragma unroll
    for (int i = 0; i < 4; i++) {
        const int row = block_row + ty * 4 + i;
#pragma unroll
        for (int j = 0; j < 4; j++) {
            const int col = block_col + tx * 4 + j;
            if (GUARD && col >= N) continue;
            float v = acc[i][j] + bias[col];
            if (RELU) v = fmaxf(v, 0.f);
            Cout[(size_t)row * N + col] = v;
            if (Cout2) Cout2[(size_t)row * N + col] = v;
        }
    }
}

// ---------------------------------------------------------------------------
extern "C" void kernel_launch(void* const* d_in, const int* in_sizes, int n_in,
                              void* d_out, int out_size)
{
    const int*   input_ids = (const int*)d_in[0];
    const int*   attn_mask = (const int*)d_in[1];
    const float* emb       = (const float*)d_in[2];
    const float* W1        = (const float*)d_in[3];
    const float* b1        = (const float*)d_in[4];
    const float* W2        = (const float*)d_in[5];
    const float* b2        = (const float*)d_in[6];
    float*       out       = (float*)d_out;

    float* bow; cudaGetSymbolAddress((void**)&bow, g_bow);
    float* h;   cudaGetSymbolAddress((void**)&h,   g_h);

    // Stage 1: pooling
    pool_kernel<<<BB, 192>>>(input_ids, attn_mask, emb, bow);

    // Stage 2: h = relu(bow @ W1 + b1)   [2048,768]
    {
        dim3 grid(DD / 64, BB / 64);   // (12, 32)
        gemm_kernel<true, false><<<grid, 256>>>(bow, W1, b1, h, nullptr, BB, DD, DD);
    }

    // Stage 3: scores = h @ W2 + b2   [2048,100], duplicated if out holds 2 copies
    {
        float* out2 = (out_size >= 2 * BB * CC) ? (out + (size_t)BB * CC) : nullptr;
        dim3 grid((CC + 63) / 64, BB / 64); // (2, 32)
        gemm_kernel<false, true><<<grid, 256>>>(h, W2, b2, out, out2, BB, CC, DD);
    }
}

// round 4
// speedup vs baseline: 1.0067x; 1.0067x over previous
#include <cuda_runtime.h>
#include <cuda_bf16.h>
#include <cstdint>

#define BB 2048
#define SS 256
#define DD 768
#define CC 100

// Scratch (no cudaMalloc allowed)
__device__ float g_bow[(size_t)BB * DD];
__device__ float g_h[(size_t)BB * DD];
__device__ float g_part[2][BB][DD];
__device__ float g_cntf[2][BB];

// ---------------------------------------------------------------------------
// Stage 1a: partial pooling. grid (BB, 2); each block sums 128 tokens.
// ---------------------------------------------------------------------------
__global__ __launch_bounds__(192) void pool_partial(
    const int* __restrict__ ids,
    const int* __restrict__ mask,
    const float* __restrict__ emb)
{
    const int b    = blockIdx.x;
    const int half = blockIdx.y;
    const int t    = threadIdx.x;   // 0..191
    const int base = half * 128;

    __shared__ int s_ids[128];
    const int* id_row = ids  + (size_t)b * SS + base;
    const int* m_row  = mask + (size_t)b * SS + base;
    for (int s = t; s < 128; s += 192)
        s_ids[s] = (m_row[s] != 0) ? id_row[s] : -1;
    __syncthreads();

    float4 acc = make_float4(0.f, 0.f, 0.f, 0.f);
    int cnt = 0;
#pragma unroll 8
    for (int s = 0; s < 128; s++) {
        int id = s_ids[s];
        if (id >= 0) {
            const float4 v = *((const float4*)(emb + (size_t)id * DD) + t);
            acc.x += v.x; acc.y += v.y; acc.z += v.z; acc.w += v.w;
            cnt++;
        }
    }
    *((float4*)(&g_part[half][b][0]) + t) = acc;
    if (t == 0) g_cntf[half][b] = (float)cnt;
}

// ---------------------------------------------------------------------------
// Stage 1b: combine halves: bow = (p0+p1)/(c0+c1)
// ---------------------------------------------------------------------------
__global__ __launch_bounds__(192) void pool_combine(float* __restrict__ bow)
{
    const int b = blockIdx.x;
    const int t = threadIdx.x;
    const float inv = 1.0f / (g_cntf[0][b] + g_cntf[1][b]);
    const float4 p0 = *((const float4*)(&g_part[0][b][0]) + t);
    const float4 p1 = *((const float4*)(&g_part[1][b][0]) + t);
    float4 v;
    v.x = (p0.x + p1.x) * inv;
    v.y = (p0.y + p1.y) * inv;
    v.z = (p0.z + p1.z) * inv;
    v.w = (p0.w + p1.w) * inv;
    *((float4*)(bow + (size_t)b * DD) + t) = v;
}

// ---------------------------------------------------------------------------
// Big fp32 GEMM: C = relu(A[M,K] @ B[K,N] + bias).
// BM=128, BN=64, BK=16, 256 threads, 8x4 per thread, double-buffered smem.
// Requires M%128==0, N%64==0, K%16==0. Used for gemm1.
// ---------------------------------------------------------------------------
__global__ __launch_bounds__(256, 2) void gemm128_kernel(
    const float* __restrict__ A,
    const float* __restrict__ Bm,
    const float* __restrict__ bias,
    float* __restrict__ Cout,
    int M, int N, int K)
{
    const int BM = 128, BN = 64, BK = 16;
    __shared__ float As[2][BK][BM + 4];   // transposed: As[k][m]
    __shared__ float Bs[2][BK][BN];

    const int tid = threadIdx.x;
    const int tx  = tid & 15;     // col group: 4 cols each
    const int ty  = tid >> 4;     // row group: 8 rows each

    const int block_row = blockIdx.y * BM;
    const int block_col = blockIdx.x * BN;

    // A tile: 128x16 = 512 float4; 2 per thread
    const int a_idx0 = tid;          // float4 index 0..255
    const int a_idx1 = tid + 256;    // 256..511
    const int a_row0 = a_idx0 >> 2, a_c40 = (a_idx0 & 3) * 4;
    const int a_row1 = a_idx1 >> 2, a_c41 = (a_idx1 & 3) * 4;
    // B tile: 16x64 = 256 float4; 1 per thread
    const int b_row = tid >> 4;
    const int b_col = (tid & 15) * 4;

    const int NT = K / BK;

    float acc[8][4];
#pragma unroll
    for (int i = 0; i < 8; i++)
#pragma unroll
        for (int j = 0; j < 4; j++) acc[i][j] = 0.f;

    // ---- preload tile 0 into buffer 0 ----
    {
        const float4 av0 = *(const float4*)(A + (size_t)(block_row + a_row0) * K + a_c40);
        const float4 av1 = *(const float4*)(A + (size_t)(block_row + a_row1) * K + a_c41);
        As[0][a_c40 + 0][a_row0] = av0.x;
        As[0][a_c40 + 1][a_row0] = av0.y;
        As[0][a_c40 + 2][a_row0] = av0.z;
        As[0][a_c40 + 3][a_row0] = av0.w;
        As[0][a_c41 + 0][a_row1] = av1.x;
        As[0][a_c41 + 1][a_row1] = av1.y;
        As[0][a_c41 + 2][a_row1] = av1.z;
        As[0][a_c41 + 3][a_row1] = av1.w;
        *(float4*)&Bs[0][b_row][b_col] =
            *(const float4*)(Bm + (size_t)b_row * N + block_col + b_col);
    }
    __syncthreads();

    for (int kt = 0; kt < NT; kt++) {
        const int cur = kt & 1;
        const int nxt = cur ^ 1;
        const bool has_next = (kt + 1 < NT);

        float4 aR0, aR1, bR;
        if (has_next) {
            const int k0 = (kt + 1) * BK;
            aR0 = *(const float4*)(A + (size_t)(block_row + a_row0) * K + k0 + a_c40);
            aR1 = *(const float4*)(A + (size_t)(block_row + a_row1) * K + k0 + a_c41);
            bR  = *(const float4*)(Bm + (size_t)(k0 + b_row) * N + block_col + b_col);
        }

#pragma unroll
        for (int k = 0; k < BK; k++) {
            float a[8], bb[4];
            const float4 av0 = *(const float4*)&As[cur][k][ty * 8 + 0];
            const float4 av1 = *(const float4*)&As[cur][k][ty * 8 + 4];
            a[0] = av0.x; a[1] = av0.y; a[2] = av0.z; a[3] = av0.w;
            a[4] = av1.x; a[5] = av1.y; a[6] = av1.z; a[7] = av1.w;
            const float4 bv = *(const float4*)&Bs[cur][k][tx * 4];
            bb[0] = bv.x; bb[1] = bv.y; bb[2] = bv.z; bb[3] = bv.w;
#pragma unroll
            for (int i = 0; i < 8; i++)
#pragma unroll
                for (int j = 0; j < 4; j++)
                    acc[i][j] = fmaf(a[i], bb[j], acc[i][j]);
        }

        if (has_next) {
            As[nxt][a_c40 + 0][a_row0] = aR0.x;
            As[nxt][a_c40 + 1][a_row0] = aR0.y;
            As[nxt][a_c40 + 2][a_row0] = aR0.z;
            As[nxt][a_c40 + 3][a_row0] = aR0.w;
            As[nxt][a_c41 + 0][a_row1] = aR1.x;
            As[nxt][a_c41 + 1][a_row1] = aR1.y;
            As[nxt][a_c41 + 2][a_row1] = aR1.z;
            As[nxt][a_c41 + 3][a_row1] = aR1.w;
            *(float4*)&Bs[nxt][b_row][b_col] = bR;
            __syncthreads();
        }
    }

    // Epilogue: bias + relu, vectorized stores
    const float4 bv = *(const float4*)(bias + block_col + tx * 4);
#pragma unroll
    for (int i = 0; i < 8; i++) {
        const int row = block_row + ty * 8 + i;
        float4 v;
        v.x = fmaxf(acc[i][0] + bv.x, 0.f);
        v.y = fmaxf(acc[i][1] + bv.y, 0.f);
        v.z = fmaxf(acc[i][2] + bv.z, 0.f);
        v.w = fmaxf(acc[i][3] + bv.w, 0.f);
        *(float4*)(Cout + (size_t)row * N + block_col + tx * 4) = v;
    }
}

// ---------------------------------------------------------------------------
// Small guarded GEMM (gemm2): C = A@B + bias, N=100, duplicated output.
// BM=64, BN=64, BK=16, 256 threads, 4x4 per thread.
// ---------------------------------------------------------------------------
__global__ __launch_bounds__(256) void gemm_small_kernel(
    const float* __restrict__ A,
    const float* __restrict__ Bm,
    const float* __restrict__ bias,
    float* __restrict__ Cout,
    float* __restrict__ Cout2,
    int M, int N, int K)
{
    const int BM = 64, BN = 64, BK = 16;
    __shared__ float As[BK][BM + 4];
    __shared__ float Bs[BK][BN];

    const int tid = threadIdx.x;
    const int tx  = tid & 15;
    const int ty  = tid >> 4;

    const int block_row = blockIdx.y * BM;
    const int block_col = blockIdx.x * BN;

    const int a_row = tid >> 2;
    const int a_c4  = (tid & 3) * 4;
    const int b_row = tid >> 4;
    const int b_col = (tid & 15) * 4;

    float acc[4][4];
#pragma unroll
    for (int i = 0; i < 4; i++)
#pragma unroll
        for (int j = 0; j < 4; j++) acc[i][j] = 0.f;

    for (int k0 = 0; k0 < K; k0 += BK) {
        {
            const float4 av = *(const float4*)(A + (size_t)(block_row + a_row) * K + k0 + a_c4);
            As[a_c4 + 0][a_row] = av.x;
            As[a_c4 + 1][a_row] = av.y;
            As[a_c4 + 2][a_row] = av.z;
            As[a_c4 + 3][a_row] = av.w;
        }
        {
            const int col = block_col + b_col;
            const float* src = Bm + (size_t)(k0 + b_row) * N;
            Bs[b_row][b_col + 0] = (col + 0 < N) ? src[col + 0] : 0.f;
            Bs[b_row][b_col + 1] = (col + 1 < N) ? src[col + 1] : 0.f;
            Bs[b_row][b_col + 2] = (col + 2 < N) ? src[col + 2] : 0.f;
            Bs[b_row][b_col + 3] = (col + 3 < N) ? src[col + 3] : 0.f;
        }
        __syncthreads();

#pragma unroll
        for (int k = 0; k < BK; k++) {
            float a[4], bb[4];
#pragma unroll
            for (int i = 0; i < 4; i++) a[i]  = As[k][ty * 4 + i];
#pragma unroll
            for (int j = 0; j < 4; j++) bb[j] = Bs[k][tx * 4 + j];
#pragma unroll
            for (int i = 0; i < 4; i++)
#pragma unroll
                for (int j = 0; j < 4; j++)
                    acc[i][j] = fmaf(a[i], bb[j], acc[i][j]);
        }
        __syncthreads();
    }

#pragma unroll
    for (int i = 0; i < 4; i++) {
        const int row = block_row + ty * 4 + i;
#pragma unroll
        for (int j = 0; j < 4; j++) {
            const int col = block_col + tx * 4 + j;
            if (col >= N) continue;
            float v = acc[i][j] + bias[col];
            Cout[(size_t)row * N + col] = v;
            if (Cout2) Cout2[(size_t)row * N + col] = v;
        }
    }
}

// ---------------------------------------------------------------------------
extern "C" void kernel_launch(void* const* d_in, const int* in_sizes, int n_in,
                              void* d_out, int out_size)
{
    const int*   input_ids = (const int*)d_in[0];
    const int*   attn_mask = (const int*)d_in[1];
    const float* emb       = (const float*)d_in[2];
    const float* W1        = (const float*)d_in[3];
    const float* b1        = (const float*)d_in[4];
    const float* W2        = (const float*)d_in[5];
    const float* b2        = (const float*)d_in[6];
    float*       out       = (float*)d_out;

    float* bow; cudaGetSymbolAddress((void**)&bow, g_bow);
    float* h;   cudaGetSymbolAddress((void**)&h,   g_h);

    // Stage 1: pooling (split over sequence halves, then combine)
    {
        dim3 grid(BB, 2);
        pool_partial<<<grid, 192>>>(input_ids, attn_mask, emb);
        pool_combine<<<BB, 192>>>(bow);
    }

    // Stage 2: h = relu(bow @ W1 + b1)   [2048,768]
    {
        dim3 grid(DD / 64, BB / 128);   // (12, 16)
        gemm128_kernel<<<grid, 256>>>(bow, W1, b1, h, BB, DD, DD);
    }

    // Stage 3: scores = h @ W2 + b2   [2048,100], duplicated
    {
        float* out2 = (out_size >= 2 * BB * CC) ? (out + (size_t)BB * CC) : nullptr;
        dim3 grid((CC + 63) / 64, BB / 64); // (2, 32)
        gemm_small_kernel<<<grid, 256>>>(h, W2, b2, out, out2, BB, CC, DD);
    }
}

// round 5
// speedup vs baseline: 1.1256x; 1.1180x over previous
#include <cuda_runtime.h>
#include <cuda_bf16.h>
#include <cstdint>

#define BB 2048
#define SS 256
#define DD 768
#define CC 100
#define KSL 6          // K slices for gemm2 split-K
#define NP 128         // padded N for gemm2

// Scratch (no cudaMalloc allowed)
__device__ float g_bow[(size_t)BB * DD];
__device__ float g_h[(size_t)BB * DD];
__device__ float g_part[2][BB][DD];
__device__ float g_cntf[2][BB];
__device__ float g_p2[KSL][BB][NP];

// ---------------------------------------------------------------------------
// Stage 1a: partial pooling. grid (BB, 2); each block sums 128 tokens.
// ---------------------------------------------------------------------------
__global__ __launch_bounds__(192) void pool_partial(
    const int* __restrict__ ids,
    const int* __restrict__ mask,
    const float* __restrict__ emb)
{
    const int b    = blockIdx.x;
    const int half = blockIdx.y;
    const int t    = threadIdx.x;   // 0..191
    const int base = half * 128;

    __shared__ int s_ids[128];
    const int* id_row = ids  + (size_t)b * SS + base;
    const int* m_row  = mask + (size_t)b * SS + base;
    for (int s = t; s < 128; s += 192)
        s_ids[s] = (m_row[s] != 0) ? id_row[s] : -1;
    __syncthreads();

    float4 acc = make_float4(0.f, 0.f, 0.f, 0.f);
    int cnt = 0;
#pragma unroll 8
    for (int s = 0; s < 128; s++) {
        int id = s_ids[s];
        if (id >= 0) {
            const float4 v = *((const float4*)(emb + (size_t)id * DD) + t);
            acc.x += v.x; acc.y += v.y; acc.z += v.z; acc.w += v.w;
            cnt++;
        }
    }
    *((float4*)(&g_part[half][b][0]) + t) = acc;
    if (t == 0) g_cntf[half][b] = (float)cnt;
}

// ---------------------------------------------------------------------------
// Stage 1b: combine halves: bow = (p0+p1)/(c0+c1)
// ---------------------------------------------------------------------------
__global__ __launch_bounds__(192) void pool_combine(float* __restrict__ bow)
{
    const int b = blockIdx.x;
    const int t = threadIdx.x;
    const float inv = 1.0f / (g_cntf[0][b] + g_cntf[1][b]);
    const float4 p0 = *((const float4*)(&g_part[0][b][0]) + t);
    const float4 p1 = *((const float4*)(&g_part[1][b][0]) + t);
    float4 v;
    v.x = (p0.x + p1.x) * inv;
    v.y = (p0.y + p1.y) * inv;
    v.z = (p0.z + p1.z) * inv;
    v.w = (p0.w + p1.w) * inv;
    *((float4*)(bow + (size_t)b * DD) + t) = v;
}

// ---------------------------------------------------------------------------
// Big fp32 GEMM: C = relu(A[M,K] @ B[K,N] + bias).
// BM=128, BN=64, BK=16, 256 threads, 8x4 per thread, double-buffered smem.
// ---------------------------------------------------------------------------
__global__ __launch_bounds__(256, 2) void gemm128_kernel(
    const float* __restrict__ A,
    const float* __restrict__ Bm,
    const float* __restrict__ bias,
    float* __restrict__ Cout,
    int M, int N, int K)
{
    const int BM = 128, BN = 64, BK = 16;
    __shared__ float As[2][BK][BM + 4];
    __shared__ float Bs[2][BK][BN];

    const int tid = threadIdx.x;
    const int tx  = tid & 15;
    const int ty  = tid >> 4;

    const int block_row = blockIdx.y * BM;
    const int block_col = blockIdx.x * BN;

    const int a_idx0 = tid;
    const int a_idx1 = tid + 256;
    const int a_row0 = a_idx0 >> 2, a_c40 = (a_idx0 & 3) * 4;
    const int a_row1 = a_idx1 >> 2, a_c41 = (a_idx1 & 3) * 4;
    const int b_row = tid >> 4;
    const int b_col = (tid & 15) * 4;

    const int NT = K / BK;

    float acc[8][4];
#pragma unroll
    for (int i = 0; i < 8; i++)
#pragma unroll
        for (int j = 0; j < 4; j++) acc[i][j] = 0.f;

    {
        const float4 av0 = *(const float4*)(A + (size_t)(block_row + a_row0) * K + a_c40);
        const float4 av1 = *(const float4*)(A + (size_t)(block_row + a_row1) * K + a_c41);
        As[0][a_c40 + 0][a_row0] = av0.x;
        As[0][a_c40 + 1][a_row0] = av0.y;
        As[0][a_c40 + 2][a_row0] = av0.z;
        As[0][a_c40 + 3][a_row0] = av0.w;
        As[0][a_c41 + 0][a_row1] = av1.x;
        As[0][a_c41 + 1][a_row1] = av1.y;
        As[0][a_c41 + 2][a_row1] = av1.z;
        As[0][a_c41 + 3][a_row1] = av1.w;
        *(float4*)&Bs[0][b_row][b_col] =
            *(const float4*)(Bm + (size_t)b_row * N + block_col + b_col);
    }
    __syncthreads();

    for (int kt = 0; kt < NT; kt++) {
        const int cur = kt & 1;
        const int nxt = cur ^ 1;
        const bool has_next = (kt + 1 < NT);

        float4 aR0, aR1, bR;
        if (has_next) {
            const int k0 = (kt + 1) * BK;
            aR0 = *(const float4*)(A + (size_t)(block_row + a_row0) * K + k0 + a_c40);
            aR1 = *(const float4*)(A + (size_t)(block_row + a_row1) * K + k0 + a_c41);
            bR  = *(const float4*)(Bm + (size_t)(k0 + b_row) * N + block_col + b_col);
        }

#pragma unroll
        for (int k = 0; k < BK; k++) {
            float a[8], bb[4];
            const float4 av0 = *(const float4*)&As[cur][k][ty * 8 + 0];
            const float4 av1 = *(const float4*)&As[cur][k][ty * 8 + 4];
            a[0] = av0.x; a[1] = av0.y; a[2] = av0.z; a[3] = av0.w;
            a[4] = av1.x; a[5] = av1.y; a[6] = av1.z; a[7] = av1.w;
            const float4 bv = *(const float4*)&Bs[cur][k][tx * 4];
            bb[0] = bv.x; bb[1] = bv.y; bb[2] = bv.z; bb[3] = bv.w;
#pragma unroll
            for (int i = 0; i < 8; i++)
#pragma unroll
                for (int j = 0; j < 4; j++)
                    acc[i][j] = fmaf(a[i], bb[j], acc[i][j]);
        }

        if (has_next) {
            As[nxt][a_c40 + 0][a_row0] = aR0.x;
            As[nxt][a_c40 + 1][a_row0] = aR0.y;
            As[nxt][a_c40 + 2][a_row0] = aR0.z;
            As[nxt][a_c40 + 3][a_row0] = aR0.w;
            As[nxt][a_c41 + 0][a_row1] = aR1.x;
            As[nxt][a_c41 + 1][a_row1] = aR1.y;
            As[nxt][a_c41 + 2][a_row1] = aR1.z;
            As[nxt][a_c41 + 3][a_row1] = aR1.w;
            *(float4*)&Bs[nxt][b_row][b_col] = bR;
            __syncthreads();
        }
    }

    const float4 bv = *(const float4*)(bias + block_col + tx * 4);
#pragma unroll
    for (int i = 0; i < 8; i++) {
        const int row = block_row + ty * 8 + i;
        float4 v;
        v.x = fmaxf(acc[i][0] + bv.x, 0.f);
        v.y = fmaxf(acc[i][1] + bv.y, 0.f);
        v.z = fmaxf(acc[i][2] + bv.z, 0.f);
        v.w = fmaxf(acc[i][3] + bv.w, 0.f);
        *(float4*)(Cout + (size_t)row * N + block_col + tx * 4) = v;
    }
}

// ---------------------------------------------------------------------------
// gemm2 split-K: partial[ksl] = A[64 rows, kslice] @ W2[kslice, 100->128pad]
// grid (KSL, BB/64) = (6, 32) = 192 blocks, 256 threads.
// Per-thread: 4 rows x 8 cols. K slice = 128, BK=16.
// ---------------------------------------------------------------------------
__global__ __launch_bounds__(256) void gemm_splitk(
    const float* __restrict__ A,     // [BB, DD] = h
    const float* __restrict__ Bm)    // [DD, CC] = W2
{
    const int BK = 16;
    __shared__ float As[BK][64 + 4];
    __shared__ float Bs[BK][NP];

    const int tid = threadIdx.x;
    const int tx  = tid & 15;     // 0..15 -> 8 cols each
    const int ty  = tid >> 4;     // 0..15 -> 4 rows each

    const int ksl       = blockIdx.x;           // 0..5
    const int block_row = blockIdx.y * 64;
    const int kbase     = ksl * (DD / KSL);     // 128 per slice

    // A tile: 64x16 = 256 float4, 1/thread
    const int a_row = tid >> 2;
    const int a_c4  = (tid & 3) * 4;
    // B tile: 16x128 = 512 floats4, 2/thread
    const int b_idx0 = tid, b_idx1 = tid + 256;
    const int b_r0 = b_idx0 >> 5, b_c0 = (b_idx0 & 31) * 4;
    const int b_r1 = b_idx1 >> 5, b_c1 = (b_idx1 & 31) * 4;

    float acc[4][8];
#pragma unroll
    for (int i = 0; i < 4; i++)
#pragma unroll
        for (int j = 0; j < 8; j++) acc[i][j] = 0.f;

    for (int k0 = 0; k0 < DD / KSL; k0 += BK) {
        // A tile
        {
            const float4 av = *(const float4*)(A + (size_t)(block_row + a_row) * DD + kbase + k0 + a_c4);
            As[a_c4 + 0][a_row] = av.x;
            As[a_c4 + 1][a_row] = av.y;
            As[a_c4 + 2][a_row] = av.z;
            As[a_c4 + 3][a_row] = av.w;
        }
        // B tile (guard cols >= CC). Row stride CC*4=400B is 16B aligned.
        {
            const float* src0 = Bm + (size_t)(kbase + k0 + b_r0) * CC;
            const float* src1 = Bm + (size_t)(kbase + k0 + b_r1) * CC;
            if (b_c0 + 3 < CC) {
                *(float4*)&Bs[b_r0][b_c0] = *(const float4*)(src0 + b_c0);
            } else {
                Bs[b_r0][b_c0 + 0] = (b_c0 + 0 < CC) ? src0[b_c0 + 0] : 0.f;
                Bs[b_r0][b_c0 + 1] = (b_c0 + 1 < CC) ? src0[b_c0 + 1] : 0.f;
                Bs[b_r0][b_c0 + 2] = (b_c0 + 2 < CC) ? src0[b_c0 + 2] : 0.f;
                Bs[b_r0][b_c0 + 3] = (b_c0 + 3 < CC) ? src0[b_c0 + 3] : 0.f;
            }
            if (b_c1 + 3 < CC) {
                *(float4*)&Bs[b_r1][b_c1] = *(const float4*)(src1 + b_c1);
            } else {
                Bs[b_r1][b_c1 + 0] = (b_c1 + 0 < CC) ? src1[b_c1 + 0] : 0.f;
                Bs[b_r1][b_c1 + 1] = (b_c1 + 1 < CC) ? src1[b_c1 + 1] : 0.f;
                Bs[b_r1][b_c1 + 2] = (b_c1 + 2 < CC) ? src1[b_c1 + 2] : 0.f;
                Bs[b_r1][b_c1 + 3] = (b_c1 + 3 < CC) ? src1[b_c1 + 3] : 0.f;
            }
        }
        __syncthreads();

#pragma unroll
        for (int k = 0; k < BK; k++) {
            float a[4], bb[8];
#pragma unroll
            for (int i = 0; i < 4; i++) a[i] = As[k][ty * 4 + i];
            const float4 bv0 = *(const float4*)&Bs[k][tx * 8 + 0];
            const float4 bv1 = *(const float4*)&Bs[k][tx * 8 + 4];
            bb[0] = bv0.x; bb[1] = bv0.y; bb[2] = bv0.z; bb[3] = bv0.w;
            bb[4] = bv1.x; bb[5] = bv1.y; bb[6] = bv1.z; bb[7] = bv1.w;
#pragma unroll
            for (int i = 0; i < 4; i++)
#pragma unroll
                for (int j = 0; j < 8; j++)
                    acc[i][j] = fmaf(a[i], bb[j], acc[i][j]);
        }
        __syncthreads();
    }

    // Store partials (padded cols included; reduce ignores col >= CC)
#pragma unroll
    for (int i = 0; i < 4; i++) {
        const int row = block_row + ty * 4 + i;
        float4 v0 = make_float4(acc[i][0], acc[i][1], acc[i][2], acc[i][3]);
        float4 v1 = make_float4(acc[i][4], acc[i][5], acc[i][6], acc[i][7]);
        *(float4*)(&g_p2[ksl][row][tx * 8 + 0]) = v0;
        *(float4*)(&g_p2[ksl][row][tx * 8 + 4]) = v1;
    }
}

// ---------------------------------------------------------------------------
// Reduce split-K partials + bias, write both output copies.
// ---------------------------------------------------------------------------
__global__ __launch_bounds__(256) void reduce_kernel(
    const float* __restrict__ bias,
    float* __restrict__ out,
    float* __restrict__ out2)
{
    const int idx = blockIdx.x * 256 + threadIdx.x;
    if (idx >= BB * CC) return;
    const int b = idx / CC;
    const int c = idx - b * CC;
    float v = bias[c];
#pragma unroll
    for (int s = 0; s < KSL; s++) v += g_p2[s][b][c];
    out[idx] = v;
    if (out2) out2[idx] = v;
}

// ---------------------------------------------------------------------------
extern "C" void kernel_launch(void* const* d_in, const int* in_sizes, int n_in,
                              void* d_out, int out_size)
{
    const int*   input_ids = (const int*)d_in[0];
    const int*   attn_mask = (const int*)d_in[1];
    const float* emb       = (const float*)d_in[2];
    const float* W1        = (const float*)d_in[3];
    const float* b1        = (const float*)d_in[4];
    const float* W2        = (const float*)d_in[5];
    const float* b2        = (const float*)d_in[6];
    float*       out       = (float*)d_out;

    float* bow; cudaGetSymbolAddress((void**)&bow, g_bow);
    float* h;   cudaGetSymbolAddress((void**)&h,   g_h);

    // Stage 1: pooling
    {
        dim3 grid(BB, 2);
        pool_partial<<<grid, 192>>>(input_ids, attn_mask, emb);
        pool_combine<<<BB, 192>>>(bow);
    }

    // Stage 2: h = relu(bow @ W1 + b1)
    {
        dim3 grid(DD / 64, BB / 128);   // (12, 16)
        gemm128_kernel<<<grid, 256>>>(bow, W1, b1, h, BB, DD, DD);
    }

    // Stage 3: scores = h @ W2 + b2 (split-K + reduce), duplicated output
    {
        dim3 grid(KSL, BB / 64);        // (6, 32) = 192 blocks
        gemm_splitk<<<grid, 256>>>(h, W2);
        float* out2 = (out_size >= 2 * BB * CC) ? (out + (size_t)BB * CC) : nullptr;
        reduce_kernel<<<(BB * CC + 255) / 256, 256>>>(b2, out, out2);
    }
}

// round 7
// speedup vs baseline: 1.5044x; 1.3366x over previous
#include <cuda_runtime.h>
#include <cuda_bf16.h>
#include <cstdint>

#define BB 2048
#define SS 256
#define DD 768
#define CC 100
#define KSL 6          // K slices for gemm2 split-K
#define NP 128         // padded N for gemm2

// Scratch (no cudaMalloc allowed)
__device__ float g_h[(size_t)BB * DD];
__device__ float g_part[2][BB][DD];
__device__ float g_cntf[2][BB];
__device__ float g_p2[KSL][BB][NP];
__device__ __nv_bfloat16 g_bow_hi[(size_t)BB * DD];
__device__ __nv_bfloat16 g_bow_lo[(size_t)BB * DD];
__device__ __nv_bfloat16 g_w1_hi[(size_t)DD * DD];
__device__ __nv_bfloat16 g_w1_lo[(size_t)DD * DD];

// ---------------------------------------------------------------------------
// Stage 1a: partial pooling. grid (BB, 2); each block sums 128 tokens.
// ---------------------------------------------------------------------------
__global__ __launch_bounds__(192) void pool_partial(
    const int* __restrict__ ids,
    const int* __restrict__ mask,
    const float* __restrict__ emb)
{
    const int b    = blockIdx.x;
    const int half = blockIdx.y;
    const int t    = threadIdx.x;   // 0..191
    const int base = half * 128;

    __shared__ int s_ids[128];
    const int* id_row = ids  + (size_t)b * SS + base;
    const int* m_row  = mask + (size_t)b * SS + base;
    for (int s = t; s < 128; s += 192)
        s_ids[s] = (m_row[s] != 0) ? id_row[s] : -1;
    __syncthreads();

    float4 acc = make_float4(0.f, 0.f, 0.f, 0.f);
    int cnt = 0;
#pragma unroll 8
    for (int s = 0; s < 128; s++) {
        int id = s_ids[s];
        if (id >= 0) {
            const float4 v = *((const float4*)(emb + (size_t)id * DD) + t);
            acc.x += v.x; acc.y += v.y; acc.z += v.z; acc.w += v.w;
            cnt++;
        }
    }
    *((float4*)(&g_part[half][b][0]) + t) = acc;
    if (t == 0) g_cntf[half][b] = (float)cnt;
}

// ---------------------------------------------------------------------------
// Stage 1b: combine halves, emit bow directly as bf16 (hi, lo) split.
// ---------------------------------------------------------------------------
__global__ __launch_bounds__(192) void pool_combine_split(void)
{
    const int b = blockIdx.x;
    const int t = threadIdx.x;
    const float inv = 1.0f / (g_cntf[0][b] + g_cntf[1][b]);
    const float4 p0 = *((const float4*)(&g_part[0][b][0]) + t);
    const float4 p1 = *((const float4*)(&g_part[1][b][0]) + t);
    float v[4];
    v[0] = (p0.x + p1.x) * inv;
    v[1] = (p0.y + p1.y) * inv;
    v[2] = (p0.z + p1.z) * inv;
    v[3] = (p0.w + p1.w) * inv;

    unsigned short hi[4], lo[4];
#pragma unroll
    for (int c = 0; c < 4; c++) {
        __nv_bfloat16 hb = __float2bfloat16(v[c]);
        float r = v[c] - __bfloat162float(hb);
        __nv_bfloat16 lb = __float2bfloat16(r);
        hi[c] = __bfloat16_as_ushort(hb);
        lo[c] = __bfloat16_as_ushort(lb);
    }
    const size_t idx = (size_t)b * DD + t * 4;
    uint2 ph = make_uint2(((uint32_t)hi[1] << 16) | hi[0], ((uint32_t)hi[3] << 16) | hi[2]);
    uint2 pl = make_uint2(((uint32_t)lo[1] << 16) | lo[0], ((uint32_t)lo[3] << 16) | lo[2]);
    *(uint2*)(g_bow_hi + idx) = ph;
    *(uint2*)(g_bow_lo + idx) = pl;
}

// ---------------------------------------------------------------------------
// Convert W1 fp32 -> (hi, lo) bf16 pair.
// ---------------------------------------------------------------------------
__global__ __launch_bounds__(256) void convert_w1(const float* __restrict__ W1)
{
    const int i = (blockIdx.x * 256 + threadIdx.x) * 4;
    const float4 v4 = *(const float4*)(W1 + i);
    const float v[4] = {v4.x, v4.y, v4.z, v4.w};
    unsigned short hi[4], lo[4];
#pragma unroll
    for (int c = 0; c < 4; c++) {
        __nv_bfloat16 hb = __float2bfloat16(v[c]);
        float r = v[c] - __bfloat162float(hb);
        __nv_bfloat16 lb = __float2bfloat16(r);
        hi[c] = __bfloat16_as_ushort(hb);
        lo[c] = __bfloat16_as_ushort(lb);
    }
    uint2 ph = make_uint2(((uint32_t)hi[1] << 16) | hi[0], ((uint32_t)hi[3] << 16) | hi[2]);
    uint2 pl = make_uint2(((uint32_t)lo[1] << 16) | lo[0], ((uint32_t)lo[3] << 16) | lo[2]);
    *(uint2*)(g_w1_hi + i) = ph;
    *(uint2*)(g_w1_lo + i) = pl;
}

// ---------------------------------------------------------------------------
// Tensor-core helpers
// ---------------------------------------------------------------------------
__device__ __forceinline__ uint32_t smem_u32(const void* p)
{
    return (uint32_t)__cvta_generic_to_shared(p);
}
__device__ __forceinline__ void ldsm4(uint32_t* r, uint32_t a)
{
    asm volatile("ldmatrix.sync.aligned.m8n8.x4.shared.b16 {%0,%1,%2,%3},[%4];"
                 : "=r"(r[0]), "=r"(r[1]), "=r"(r[2]), "=r"(r[3]) : "r"(a));
}
__device__ __forceinline__ void ldsm4t(uint32_t* r, uint32_t a)
{
    asm volatile("ldmatrix.sync.aligned.m8n8.x4.trans.shared.b16 {%0,%1,%2,%3},[%4];"
                 : "=r"(r[0]), "=r"(r[1]), "=r"(r[2]), "=r"(r[3]) : "r"(a));
}
__device__ __forceinline__ void mma_bf16(float* d, const uint32_t* a, const uint32_t* b)
{
    asm volatile(
        "mma.sync.aligned.m16n8k16.row.col.f32.bf16.bf16.f32 "
        "{%0,%1,%2,%3}, {%4,%5,%6,%7}, {%8,%9}, {%0,%1,%2,%3};"
        : "+f"(d[0]), "+f"(d[1]), "+f"(d[2]), "+f"(d[3])
        : "r"(a[0]), "r"(a[1]), "r"(a[2]), "r"(a[3]), "r"(b[0]), "r"(b[1]));
}

// ---------------------------------------------------------------------------
// gemm1 via tensor cores with bf16-split: h = relu(bow @ W1 + b1).
// C = Ahi*Bhi + Ahi*Blo + Alo*Bhi (fp32 accum).
// BM=64, BN=128, BK=16. 8 warps. grid (6, 32) = 192 blocks.
// ---------------------------------------------------------------------------
#define AST 24    // A smem row stride (halves) = 48 B: 16B-aligned rows, conflict-free
#define BST 136   // B smem row stride (halves) = 272 B: 16B-aligned rows, conflict-free

__global__ __launch_bounds__(256, 2) void gemm1_mma(
    const float* __restrict__ bias,
    float* __restrict__ h)
{
    __shared__ __align__(16) __nv_bfloat16 sA[2][2][64 * AST];
    __shared__ __align__(16) __nv_bfloat16 sB[2][2][16 * BST];

    const int tid    = threadIdx.x;
    const int lane   = tid & 31;
    const int wid    = tid >> 5;
    const int warp_m = wid & 1;     // 0..1
    const int warp_n = wid >> 1;    // 0..3

    const int block_row = blockIdx.y * 64;
    const int block_col = blockIdx.x * 128;

    // ---- fill mappings ----
    const int ap = tid >> 7;            // 0: hi, 1: lo
    const int ar = (tid & 127) >> 1;    // 0..63
    const int ac = (tid & 1) * 8;       // 0 or 8
    const int brr = tid >> 4;           // 0..15
    const int bcc = (tid & 15) * 8;     // 0..120

    const __nv_bfloat16* Asrc = (ap ? g_bow_lo : g_bow_hi)
                                + (size_t)(block_row + ar) * DD + ac;
    const __nv_bfloat16* Bh = g_w1_hi + (size_t)brr * DD + block_col + bcc;
    const __nv_bfloat16* Bl = g_w1_lo + (size_t)brr * DD + block_col + bcc;

    float acc[2][4][4];
#pragma unroll
    for (int mt = 0; mt < 2; mt++)
#pragma unroll
        for (int nt = 0; nt < 4; nt++)
#pragma unroll
            for (int q = 0; q < 4; q++) acc[mt][nt][q] = 0.f;

    // ---- preload k-tile 0 into stage 0 ----
    {
        uint4 pa = *(const uint4*)(Asrc);
        uint4 ph = *(const uint4*)(Bh);
        uint4 pl = *(const uint4*)(Bl);
        *(uint4*)&sA[0][ap][ar * AST + ac] = pa;
        *(uint4*)&sB[0][0][brr * BST + bcc] = ph;
        *(uint4*)&sB[0][1][brr * BST + bcc] = pl;
    }
    __syncthreads();

    const int NT = DD / 16;   // 48
    int aoff[2];
#pragma unroll
    for (int mt = 0; mt < 2; mt++)
        aoff[mt] = (warp_m * 32 + mt * 16 + (lane & 15)) * AST + (lane >> 4) * 8;
    int boff[2];
#pragma unroll
    for (int g = 0; g < 2; g++)
        boff[g] = (lane & 15) * BST + warp_n * 32 + g * 16 + (lane >> 4) * 8;

    for (int kt = 0; kt < NT; kt++) {
        const int cur = kt & 1;
        const int nxt = cur ^ 1;
        const bool has_next = (kt + 1 < NT);

        uint4 pa, ph, pl;
        if (has_next) {
            const int k0 = (kt + 1) * 16;
            pa = *(const uint4*)(Asrc + k0);
            ph = *(const uint4*)(Bh + (size_t)k0 * DD);
            pl = *(const uint4*)(Bl + (size_t)k0 * DD);
        }

        // ---- compute from stage cur ----
        uint32_t af[2][2][4];     // [p][mt]
#pragma unroll
        for (int p = 0; p < 2; p++)
#pragma unroll
            for (int mt = 0; mt < 2; mt++)
                ldsm4(af[p][mt], smem_u32(&sA[cur][p][aoff[mt]]));

        uint32_t bfr[2][4][2];    // [p][nt]
#pragma unroll
        for (int p = 0; p < 2; p++)
#pragma unroll
            for (int g = 0; g < 2; g++) {
                uint32_t r[4];
                ldsm4t(r, smem_u32(&sB[cur][p][boff[g]]));
                bfr[p][2 * g + 0][0] = r[0]; bfr[p][2 * g + 0][1] = r[1];
                bfr[p][2 * g + 1][0] = r[2]; bfr[p][2 * g + 1][1] = r[3];
            }

#pragma unroll
        for (int mt = 0; mt < 2; mt++)
#pragma unroll
            for (int nt = 0; nt < 4; nt++) {
                mma_bf16(acc[mt][nt], af[0][mt], bfr[0][nt]);  // hi*hi
                mma_bf16(acc[mt][nt], af[0][mt], bfr[1][nt]);  // hi*lo
                mma_bf16(acc[mt][nt], af[1][mt], bfr[0][nt]);  // lo*hi
            }

        if (has_next) {
            *(uint4*)&sA[nxt][ap][ar * AST + ac] = pa;
            *(uint4*)&sB[nxt][0][brr * BST + bcc] = ph;
            *(uint4*)&sB[nxt][1][brr * BST + bcc] = pl;
            __syncthreads();
        }
    }

    // ---- epilogue: bias + relu ----
#pragma unroll
    for (int mt = 0; mt < 2; mt++) {
        const int row0 = block_row + warp_m * 32 + mt * 16 + (lane >> 2);
#pragma unroll
        for (int nt = 0; nt < 4; nt++) {
            const int col = block_col + warp_n * 32 + nt * 8 + (lane & 3) * 2;
            const float b0 = bias[col], b1v = bias[col + 1];
            float2 v0, v1;
            v0.x = fmaxf(acc[mt][nt][0] + b0, 0.f);
            v0.y = fmaxf(acc[mt][nt][1] + b1v, 0.f);
            v1.x = fmaxf(acc[mt][nt][2] + b0, 0.f);
            v1.y = fmaxf(acc[mt][nt][3] + b1v, 0.f);
            *(float2*)(h + (size_t)row0 * DD + col)       = v0;
            *(float2*)(h + (size_t)(row0 + 8) * DD + col) = v1;
        }
    }
}

// ---------------------------------------------------------------------------
// gemm2 split-K (fp32 SIMT): partial[ksl] = h[64 rows, kslice] @ W2[kslice, :]
// ---------------------------------------------------------------------------
__global__ __launch_bounds__(256) void gemm_splitk(
    const float* __restrict__ A,
    const float* __restrict__ Bm)
{
    const int BK = 16;
    __shared__ float As[BK][64 + 4];
    __shared__ float Bs[BK][NP];

    const int tid = threadIdx.x;
    const int tx  = tid & 15;
    const int ty  = tid >> 4;

    const int ksl       = blockIdx.x;
    const int block_row = blockIdx.y * 64;
    const int kbase     = ksl * (DD / KSL);

    const int a_row = tid >> 2;
    const int a_c4  = (tid & 3) * 4;
    const int b_idx0 = tid, b_idx1 = tid + 256;
    const int b_r0 = b_idx0 >> 5, b_c0 = (b_idx0 & 31) * 4;
    const int b_r1 = b_idx1 >> 5, b_c1 = (b_idx1 & 31) * 4;

    float acc[4][8];
#pragma unroll
    for (int i = 0; i < 4; i++)
#pragma unroll
        for (int j = 0; j < 8; j++) acc[i][j] = 0.f;

    for (int k0 = 0; k0 < DD / KSL; k0 += BK) {
        {
            const float4 av = *(const float4*)(A + (size_t)(block_row + a_row) * DD + kbase + k0 + a_c4);
            As[a_c4 + 0][a_row] = av.x;
            As[a_c4 + 1][a_row] = av.y;
            As[a_c4 + 2][a_row] = av.z;
            As[a_c4 + 3][a_row] = av.w;
        }
        {
            const float* src0 = Bm + (size_t)(kbase + k0 + b_r0) * CC;
            const float* src1 = Bm + (size_t)(kbase + k0 + b_r1) * CC;
            if (b_c0 + 3 < CC) {
                *(float4*)&Bs[b_r0][b_c0] = *(const float4*)(src0 + b_c0);
            } else {
                Bs[b_r0][b_c0 + 0] = (b_c0 + 0 < CC) ? src0[b_c0 + 0] : 0.f;
                Bs[b_r0][b_c0 + 1] = (b_c0 + 1 < CC) ? src0[b_c0 + 1] : 0.f;
                Bs[b_r0][b_c0 + 2] = (b_c0 + 2 < CC) ? src0[b_c0 + 2] : 0.f;
                Bs[b_r0][b_c0 + 3] = (b_c0 + 3 < CC) ? src0[b_c0 + 3] : 0.f;
            }
            if (b_c1 + 3 < CC) {
                *(float4*)&Bs[b_r1][b_c1] = *(const float4*)(src1 + b_c1);
            } else {
                Bs[b_r1][b_c1 + 0] = (b_c1 + 0 < CC) ? src1[b_c1 + 0] : 0.f;
                Bs[b_r1][b_c1 + 1] = (b_c1 + 1 < CC) ? src1[b_c1 + 1] : 0.f;
                Bs[b_r1][b_c1 + 2] = (b_c1 + 2 < CC) ? src1[b_c1 + 2] : 0.f;
                Bs[b_r1][b_c1 + 3] = (b_c1 + 3 < CC) ? src1[b_c1 + 3] : 0.f;
            }
        }
        __syncthreads();

#pragma unroll
        for (int k = 0; k < BK; k++) {
            float a[4], bb[8];
#pragma unroll
            for (int i = 0; i < 4; i++) a[i] = As[k][ty * 4 + i];
            const float4 bv0 = *(const float4*)&Bs[k][tx * 8 + 0];
            const float4 bv1 = *(const float4*)&Bs[k][tx * 8 + 4];
            bb[0] = bv0.x; bb[1] = bv0.y; bb[2] = bv0.z; bb[3] = bv0.w;
            bb[4] = bv1.x; bb[5] = bv1.y; bb[6] = bv1.z; bb[7] = bv1.w;
#pragma unroll
            for (int i = 0; i < 4; i++)
#pragma unroll
                for (int j = 0; j < 8; j++)
                    acc[i][j] = fmaf(a[i], bb[j], acc[i][j]);
        }
        __syncthreads();
    }

#pragma unroll
    for (int i = 0; i < 4; i++) {
        const int row = block_row + ty * 4 + i;
        float4 v0 = make_float4(acc[i][0], acc[i][1], acc[i][2], acc[i][3]);
        float4 v1 = make_float4(acc[i][4], acc[i][5], acc[i][6], acc[i][7]);
        *(float4*)(&g_p2[ksl][row][tx * 8 + 0]) = v0;
        *(float4*)(&g_p2[ksl][row][tx * 8 + 4]) = v1;
    }
}

// ---------------------------------------------------------------------------
// Reduce split-K partials + bias, write both output copies.
// ---------------------------------------------------------------------------
__global__ __launch_bounds__(256) void reduce_kernel(
    const float* __restrict__ bias,
    float* __restrict__ out,
    float* __restrict__ out2)
{
    const int idx = blockIdx.x * 256 + threadIdx.x;
    if (idx >= BB * CC) return;
    const int b = idx / CC;
    const int c = idx - b * CC;
    float v = bias[c];
#pragma unroll
    for (int s = 0; s < KSL; s++) v += g_p2[s][b][c];
    out[idx] = v;
    if (out2) out2[idx] = v;
}

// ---------------------------------------------------------------------------
extern "C" void kernel_launch(void* const* d_in, const int* in_sizes, int n_in,
                              void* d_out, int out_size)
{
    const int*   input_ids = (const int*)d_in[0];
    const int*   attn_mask = (const int*)d_in[1];
    const float* emb       = (const float*)d_in[2];
    const float* W1        = (const float*)d_in[3];
    const float* b1        = (const float*)d_in[4];
    const float* W2        = (const float*)d_in[5];
    const float* b2        = (const float*)d_in[6];
    float*       out       = (float*)d_out;

    float* h; cudaGetSymbolAddress((void**)&h, g_h);

    // W1 -> bf16 hi/lo (independent; launch first)
    convert_w1<<<(DD * DD) / (256 * 4), 256>>>(W1);

    // Stage 1: pooling (emit bow directly as bf16 hi/lo)
    {
        dim3 grid(BB, 2);
        pool_partial<<<grid, 192>>>(input_ids, attn_mask, emb);
        pool_combine_split<<<BB, 192>>>();
    }

    // Stage 2: h = relu(bow @ W1 + b1), tensor cores, bf16-split x3
    {
        dim3 grid(DD / 128, BB / 64);   // (6, 32)
        gemm1_mma<<<grid, 256>>>(b1, h);
    }

    // Stage 3: scores = h @ W2 + b2 (split-K + reduce), duplicated output
    {
        dim3 grid(KSL, BB / 64);        // (6, 32)
        gemm_splitk<<<grid, 256>>>(h, W2);
        float* out2 = (out_size >= 2 * BB * CC) ? (out + (size_t)BB * CC) : nullptr;
        reduce_kernel<<<(BB * CC + 255) / 256, 256>>>(b2, out, out2);
    }
}

// round 8
// speedup vs baseline: 1.5052x; 1.0005x over previous
#include <cuda_runtime.h>
#include <cuda_bf16.h>
#include <cstdint>

#define BB 2048
#define SS 256
#define DD 768
#define CC 100
#define KSL 12         // K slices for gemm2 split-K (slice = 64)
#define NP 128         // padded N for gemm2
#define PSL 4          // pooling sequence slices (64 tokens each)

// Scratch (no cudaMalloc allowed)
__device__ float g_h[(size_t)BB * DD];
__device__ float g_part[PSL][BB][DD];
__device__ float g_cntf[PSL][BB];
__device__ float g_p2[KSL][BB][NP];
__device__ __nv_bfloat16 g_bow_hi[(size_t)BB * DD];
__device__ __nv_bfloat16 g_bow_lo[(size_t)BB * DD];
__device__ __nv_bfloat16 g_w1_hi[(size_t)DD * DD];
__device__ __nv_bfloat16 g_w1_lo[(size_t)DD * DD];

// ---------------------------------------------------------------------------
// Stage 1a: partial pooling. grid (BB, PSL); each block sums 64 tokens.
// Valid ids are compacted into smem (order-free: sum is commutative), so the
// gather loop is branch-free and batches 4 independent row loads (MLP=4).
// ---------------------------------------------------------------------------
__global__ __launch_bounds__(192) void pool_partial(
    const int* __restrict__ ids,
    const int* __restrict__ mask,
    const float* __restrict__ emb)
{
    const int b  = blockIdx.x;
    const int sl = blockIdx.y;      // 0..3
    const int t  = threadIdx.x;     // 0..191

    __shared__ int s_ids[64];
    __shared__ int s_cnt;
    if (t == 0) s_cnt = 0;
    __syncthreads();

    if (t < 64) {
        const int off = b * SS + sl * 64 + t;
        if (mask[off] != 0) {
            const int pos = atomicAdd(&s_cnt, 1);
            s_ids[pos] = ids[off];
        }
    }
    __syncthreads();
    const int cnt = s_cnt;

    float4 acc = make_float4(0.f, 0.f, 0.f, 0.f);
    int s = 0;
    for (; s + 4 <= cnt; s += 4) {
        const float4 v0 = *((const float4*)(emb + (size_t)s_ids[s + 0] * DD) + t);
        const float4 v1 = *((const float4*)(emb + (size_t)s_ids[s + 1] * DD) + t);
        const float4 v2 = *((const float4*)(emb + (size_t)s_ids[s + 2] * DD) + t);
        const float4 v3 = *((const float4*)(emb + (size_t)s_ids[s + 3] * DD) + t);
        acc.x += (v0.x + v1.x) + (v2.x + v3.x);
        acc.y += (v0.y + v1.y) + (v2.y + v3.y);
        acc.z += (v0.z + v1.z) + (v2.z + v3.z);
        acc.w += (v0.w + v1.w) + (v2.w + v3.w);
    }
    for (; s < cnt; s++) {
        const float4 v = *((const float4*)(emb + (size_t)s_ids[s] * DD) + t);
        acc.x += v.x; acc.y += v.y; acc.z += v.z; acc.w += v.w;
    }
    *((float4*)(&g_part[sl][b][0]) + t) = acc;
    if (t == 0) g_cntf[sl][b] = (float)cnt;
}

// ---------------------------------------------------------------------------
// Stage 1b: combine slices, emit bow directly as bf16 (hi, lo) split.
// ---------------------------------------------------------------------------
__global__ __launch_bounds__(192) void pool_combine_split(void)
{
    const int b = blockIdx.x;
    const int t = threadIdx.x;
    const float inv = 1.0f / (g_cntf[0][b] + g_cntf[1][b] + g_cntf[2][b] + g_cntf[3][b]);
    float v[4] = {0.f, 0.f, 0.f, 0.f};
#pragma unroll
    for (int sl = 0; sl < PSL; sl++) {
        const float4 p = *((const float4*)(&g_part[sl][b][0]) + t);
        v[0] += p.x; v[1] += p.y; v[2] += p.z; v[3] += p.w;
    }
#pragma unroll
    for (int c = 0; c < 4; c++) v[c] *= inv;

    unsigned short hi[4], lo[4];
#pragma unroll
    for (int c = 0; c < 4; c++) {
        __nv_bfloat16 hb = __float2bfloat16(v[c]);
        float r = v[c] - __bfloat162float(hb);
        __nv_bfloat16 lb = __float2bfloat16(r);
        hi[c] = __bfloat16_as_ushort(hb);
        lo[c] = __bfloat16_as_ushort(lb);
    }
    const size_t idx = (size_t)b * DD + t * 4;
    uint2 ph = make_uint2(((uint32_t)hi[1] << 16) | hi[0], ((uint32_t)hi[3] << 16) | hi[2]);
    uint2 pl = make_uint2(((uint32_t)lo[1] << 16) | lo[0], ((uint32_t)lo[3] << 16) | lo[2]);
    *(uint2*)(g_bow_hi + idx) = ph;
    *(uint2*)(g_bow_lo + idx) = pl;
}

// ---------------------------------------------------------------------------
// Convert W1 fp32 -> (hi, lo) bf16 pair.
// ---------------------------------------------------------------------------
__global__ __launch_bounds__(256) void convert_w1(const float* __restrict__ W1)
{
    const int i = (blockIdx.x * 256 + threadIdx.x) * 4;
    const float4 v4 = *(const float4*)(W1 + i);
    const float v[4] = {v4.x, v4.y, v4.z, v4.w};
    unsigned short hi[4], lo[4];
#pragma unroll
    for (int c = 0; c < 4; c++) {
        __nv_bfloat16 hb = __float2bfloat16(v[c]);
        float r = v[c] - __bfloat162float(hb);
        __nv_bfloat16 lb = __float2bfloat16(r);
        hi[c] = __bfloat16_as_ushort(hb);
        lo[c] = __bfloat16_as_ushort(lb);
    }
    uint2 ph = make_uint2(((uint32_t)hi[1] << 16) | hi[0], ((uint32_t)hi[3] << 16) | hi[2]);
    uint2 pl = make_uint2(((uint32_t)lo[1] << 16) | lo[0], ((uint32_t)lo[3] << 16) | lo[2]);
    *(uint2*)(g_w1_hi + i) = ph;
    *(uint2*)(g_w1_lo + i) = pl;
}

// ---------------------------------------------------------------------------
// Tensor-core helpers
// ---------------------------------------------------------------------------
__device__ __forceinline__ uint32_t smem_u32(const void* p)
{
    return (uint32_t)__cvta_generic_to_shared(p);
}
__device__ __forceinline__ void ldsm4(uint32_t* r, uint32_t a)
{
    asm volatile("ldmatrix.sync.aligned.m8n8.x4.shared.b16 {%0,%1,%2,%3},[%4];"
                 : "=r"(r[0]), "=r"(r[1]), "=r"(r[2]), "=r"(r[3]) : "r"(a));
}
__device__ __forceinline__ void ldsm4t(uint32_t* r, uint32_t a)
{
    asm volatile("ldmatrix.sync.aligned.m8n8.x4.trans.shared.b16 {%0,%1,%2,%3},[%4];"
                 : "=r"(r[0]), "=r"(r[1]), "=r"(r[2]), "=r"(r[3]) : "r"(a));
}
__device__ __forceinline__ void mma_bf16(float* d, const uint32_t* a, const uint32_t* b)
{
    asm volatile(
        "mma.sync.aligned.m16n8k16.row.col.f32.bf16.bf16.f32 "
        "{%0,%1,%2,%3}, {%4,%5,%6,%7}, {%8,%9}, {%0,%1,%2,%3};"
        : "+f"(d[0]), "+f"(d[1]), "+f"(d[2]), "+f"(d[3])
        : "r"(a[0]), "r"(a[1]), "r"(a[2]), "r"(a[3]), "r"(b[0]), "r"(b[1]));
}

// ---------------------------------------------------------------------------
// gemm1 via tensor cores with bf16-split: h = relu(bow @ W1 + b1).
// C = Ahi*Bhi + Ahi*Blo + Alo*Bhi (fp32 accum).
// BM=64, BN=64, BK=16. 8 warps (2x4); warp tile 32x16.
// grid (12, 32) = 384 blocks.
// ---------------------------------------------------------------------------
#define AST 24    // A smem row stride (halves) = 48 B
#define BST 72    // B smem row stride (halves) = 144 B (16B mult, conflict-free)

__global__ __launch_bounds__(256, 2) void gemm1_mma(
    const float* __restrict__ bias,
    float* __restrict__ h)
{
    __shared__ __align__(16) __nv_bfloat16 sA[2][2][64 * AST];
    __shared__ __align__(16) __nv_bfloat16 sB[2][2][16 * BST];

    const int tid    = threadIdx.x;
    const int lane   = tid & 31;
    const int wid    = tid >> 5;
    const int warp_m = wid & 1;     // 0..1 (32 rows)
    const int warp_n = wid >> 1;    // 0..3 (16 cols)

    const int block_row = blockIdx.y * 64;
    const int block_col = blockIdx.x * 64;

    // ---- fill mappings (1 uint4 per thread for each of A, B) ----
    const int ap = tid >> 7;            // plane: 0 hi, 1 lo
    const int ar = (tid & 127) >> 1;    // 0..63
    const int ac = (tid & 1) * 8;       // 0 or 8
    const int bp = tid >> 7;
    const int bi = tid & 127;
    const int brr = bi >> 3;            // 0..15
    const int bcc = (bi & 7) * 8;       // 0..56

    const __nv_bfloat16* Asrc = (ap ? g_bow_lo : g_bow_hi)
                                + (size_t)(block_row + ar) * DD + ac;
    const __nv_bfloat16* Bsrc = (bp ? g_w1_lo : g_w1_hi)
                                + (size_t)brr * DD + block_col + bcc;

    float acc[2][2][4];
#pragma unroll
    for (int mt = 0; mt < 2; mt++)
#pragma unroll
        for (int nt = 0; nt < 2; nt++)
#pragma unroll
            for (int q = 0; q < 4; q++) acc[mt][nt][q] = 0.f;

    // ---- preload k-tile 0 ----
    *(uint4*)&sA[0][ap][ar * AST + ac]  = *(const uint4*)(Asrc);
    *(uint4*)&sB[0][bp][brr * BST + bcc] = *(const uint4*)(Bsrc);
    __syncthreads();

    const int NT = DD / 16;   // 48
    int aoff[2];
#pragma unroll
    for (int mt = 0; mt < 2; mt++)
        aoff[mt] = (warp_m * 32 + mt * 16 + (lane & 15)) * AST + (lane >> 4) * 8;
    const int boff = (lane & 15) * BST + warp_n * 16 + (lane >> 4) * 8;

    for (int kt = 0; kt < NT; kt++) {
        const int cur = kt & 1;
        const int nxt = cur ^ 1;
        const bool has_next = (kt + 1 < NT);

        uint4 pa, pb;
        if (has_next) {
            const int k0 = (kt + 1) * 16;
            pa = *(const uint4*)(Asrc + k0);
            pb = *(const uint4*)(Bsrc + (size_t)k0 * DD);
        }

        uint32_t af[2][2][4];     // [p][mt]
#pragma unroll
        for (int p = 0; p < 2; p++)
#pragma unroll
            for (int mt = 0; mt < 2; mt++)
                ldsm4(af[p][mt], smem_u32(&sA[cur][p][aoff[mt]]));

        uint32_t bfr[2][2][2];    // [p][nt]
#pragma unroll
        for (int p = 0; p < 2; p++) {
            uint32_t r[4];
            ldsm4t(r, smem_u32(&sB[cur][p][boff]));
            bfr[p][0][0] = r[0]; bfr[p][0][1] = r[1];
            bfr[p][1][0] = r[2]; bfr[p][1][1] = r[3];
        }

#pragma unroll
        for (int mt = 0; mt < 2; mt++)
#pragma unroll
            for (int nt = 0; nt < 2; nt++) {
                mma_bf16(acc[mt][nt], af[0][mt], bfr[0][nt]);  // hi*hi
                mma_bf16(acc[mt][nt], af[0][mt], bfr[1][nt]);  // hi*lo
                mma_bf16(acc[mt][nt], af[1][mt], bfr[0][nt]);  // lo*hi
            }

        if (has_next) {
            *(uint4*)&sA[nxt][ap][ar * AST + ac]  = pa;
            *(uint4*)&sB[nxt][bp][brr * BST + bcc] = pb;
            __syncthreads();
        }
    }

    // ---- epilogue: bias + relu ----
#pragma unroll
    for (int mt = 0; mt < 2; mt++) {
        const int row0 = block_row + warp_m * 32 + mt * 16 + (lane >> 2);
#pragma unroll
        for (int nt = 0; nt < 2; nt++) {
            const int col = block_col + warp_n * 16 + nt * 8 + (lane & 3) * 2;
            const float b0 = bias[col], b1v = bias[col + 1];
            float2 v0, v1;
            v0.x = fmaxf(acc[mt][nt][0] + b0, 0.f);
            v0.y = fmaxf(acc[mt][nt][1] + b1v, 0.f);
            v1.x = fmaxf(acc[mt][nt][2] + b0, 0.f);
            v1.y = fmaxf(acc[mt][nt][3] + b1v, 0.f);
            *(float2*)(h + (size_t)row0 * DD + col)       = v0;
            *(float2*)(h + (size_t)(row0 + 8) * DD + col) = v1;
        }
    }
}

// ---------------------------------------------------------------------------
// gemm2 split-K (fp32 SIMT): partial[ksl] = h[64 rows, kslice=64] @ W2
// grid (KSL, BB/64) = (12, 32) = 384 blocks.
// ---------------------------------------------------------------------------
__global__ __launch_bounds__(256) void gemm_splitk(
    const float* __restrict__ A,
    const float* __restrict__ Bm)
{
    const int BK = 16;
    __shared__ float As[BK][64 + 4];
    __shared__ float Bs[BK][NP];

    const int tid = threadIdx.x;
    const int tx  = tid & 15;
    const int ty  = tid >> 4;

    const int ksl       = blockIdx.x;
    const int block_row = blockIdx.y * 64;
    const int kbase     = ksl * (DD / KSL);   // 64 per slice

    const int a_row = tid >> 2;
    const int a_c4  = (tid & 3) * 4;
    const int b_idx0 = tid, b_idx1 = tid + 256;
    const int b_r0 = b_idx0 >> 5, b_c0 = (b_idx0 & 31) * 4;
    const int b_r1 = b_idx1 >> 5, b_c1 = (b_idx1 & 31) * 4;

    float acc[4][8];
#pragma unroll
    for (int i = 0; i < 4; i++)
#pragma unroll
        for (int j = 0; j < 8; j++) acc[i][j] = 0.f;

    for (int k0 = 0; k0 < DD / KSL; k0 += BK) {
        {
            const float4 av = *(const float4*)(A + (size_t)(block_row + a_row) * DD + kbase + k0 + a_c4);
            As[a_c4 + 0][a_row] = av.x;
            As[a_c4 + 1][a_row] = av.y;
            As[a_c4 + 2][a_row] = av.z;
            As[a_c4 + 3][a_row] = av.w;
        }
        {
            const float* src0 = Bm + (size_t)(kbase + k0 + b_r0) * CC;
            const float* src1 = Bm + (size_t)(kbase + k0 + b_r1) * CC;
            if (b_c0 + 3 < CC) {
                *(float4*)&Bs[b_r0][b_c0] = *(const float4*)(src0 + b_c0);
            } else {
                Bs[b_r0][b_c0 + 0] = (b_c0 + 0 < CC) ? src0[b_c0 + 0] : 0.f;
                Bs[b_r0][b_c0 + 1] = (b_c0 + 1 < CC) ? src0[b_c0 + 1] : 0.f;
                Bs[b_r0][b_c0 + 2] = (b_c0 + 2 < CC) ? src0[b_c0 + 2] : 0.f;
                Bs[b_r0][b_c0 + 3] = (b_c0 + 3 < CC) ? src0[b_c0 + 3] : 0.f;
            }
            if (b_c1 + 3 < CC) {
                *(float4*)&Bs[b_r1][b_c1] = *(const float4*)(src1 + b_c1);
            } else {
                Bs[b_r1][b_c1 + 0] = (b_c1 + 0 < CC) ? src1[b_c1 + 0] : 0.f;
                Bs[b_r1][b_c1 + 1] = (b_c1 + 1 < CC) ? src1[b_c1 + 1] : 0.f;
                Bs[b_r1][b_c1 + 2] = (b_c1 + 2 < CC) ? src1[b_c1 + 2] : 0.f;
                Bs[b_r1][b_c1 + 3] = (b_c1 + 3 < CC) ? src1[b_c1 + 3] : 0.f;
            }
        }
        __syncthreads();

#pragma unroll
        for (int k = 0; k < BK; k++) {
            float a[4], bb[8];
#pragma unroll
            for (int i = 0; i < 4; i++) a[i] = As[k][ty * 4 + i];
            const float4 bv0 = *(const float4*)&Bs[k][tx * 8 + 0];
            const float4 bv1 = *(const float4*)&Bs[k][tx * 8 + 4];
            bb[0] = bv0.x; bb[1] = bv0.y; bb[2] = bv0.z; bb[3] = bv0.w;
            bb[4] = bv1.x; bb[5] = bv1.y; bb[6] = bv1.z; bb[7] = bv1.w;
#pragma unroll
            for (int i = 0; i < 4; i++)
#pragma unroll
                for (int j = 0; j < 8; j++)
                    acc[i][j] = fmaf(a[i], bb[j], acc[i][j]);
        }
        __syncthreads();
    }

#pragma unroll
    for (int i = 0; i < 4; i++) {
        const int row = block_row + ty * 4 + i;
        float4 v0 = make_float4(acc[i][0], acc[i][1], acc[i][2], acc[i][3]);
        float4 v1 = make_float4(acc[i][4], acc[i][5], acc[i][6], acc[i][7]);
        *(float4*)(&g_p2[ksl][row][tx * 8 + 0]) = v0;
        *(float4*)(&g_p2[ksl][row][tx * 8 + 4]) = v1;
    }
}

// ---------------------------------------------------------------------------
// Reduce split-K partials + bias, write both output copies.
// ---------------------------------------------------------------------------
__global__ __launch_bounds__(256) void reduce_kernel(
    const float* __restrict__ bias,
    float* __restrict__ out,
    float* __restrict__ out2)
{
    const int idx = blockIdx.x * 256 + threadIdx.x;
    if (idx >= BB * CC) return;
    const int b = idx / CC;
    const int c = idx - b * CC;
    float v = bias[c];
#pragma unroll
    for (int s = 0; s < KSL; s++) v += g_p2[s][b][c];
    out[idx] = v;
    if (out2) out2[idx] = v;
}

// ---------------------------------------------------------------------------
extern "C" void kernel_launch(void* const* d_in, const int* in_sizes, int n_in,
                              void* d_out, int out_size)
{
    const int*   input_ids = (const int*)d_in[0];
    const int*   attn_mask = (const int*)d_in[1];
    const float* emb       = (const float*)d_in[2];
    const float* W1        = (const float*)d_in[3];
    const float* b1        = (const float*)d_in[4];
    const float* W2        = (const float*)d_in[5];
    const float* b2        = (const float*)d_in[6];
    float*       out       = (float*)d_out;

    float* h; cudaGetSymbolAddress((void**)&h, g_h);

    // W1 -> bf16 hi/lo (independent; launch first so it overlaps pooling)
    convert_w1<<<(DD * DD) / (256 * 4), 256>>>(W1);

    // Stage 1: pooling (4 sequence slices, then combine + bf16 split)
    {
        dim3 grid(BB, PSL);
        pool_partial<<<grid, 192>>>(input_ids, attn_mask, emb);
        pool_combine_split<<<BB, 192>>>();
    }

    // Stage 2: h = relu(bow @ W1 + b1), tensor cores, bf16-split x3
    {
        dim3 grid(DD / 64, BB / 64);    // (12, 32) = 384 blocks
        gemm1_mma<<<grid, 256>>>(b1, h);
    }

    // Stage 3: scores = h @ W2 + b2 (split-K + reduce), duplicated output
    {
        dim3 grid(KSL, BB / 64);        // (12, 32) = 384 blocks
        gemm_splitk<<<grid, 256>>>(h, W2);
        float* out2 = (out_size >= 2 * BB * CC) ? (out + (size_t)BB * CC) : nullptr;
        reduce_kernel<<<(BB * CC + 255) / 256, 256>>>(b2, out, out2);
    }
}